// round 2
// baseline (speedup 1.0000x reference)
#include <cuda_runtime.h>

#define N_NODES 100000
#define N_EDGES 1600000
#define NG 64
#define OUTD 32
#define NPAD (N_NODES + 128)

// ---------------- static scratch ----------------
__device__ float    g_deg[N_NODES];
__device__ float    g_dinv[N_NODES];
__device__ int      g_cnt[N_NODES];
__device__ int      g_rowptr[N_NODES + 1];
__device__ int      g_cursor[N_NODES];
__device__ int      g_csrc[N_EDGES];
__device__ float    g_cw[N_EDGES];
__device__ int      g_is64;

__device__ double   g_bnsum[64], g_bnss[64];
__device__ float    g_psum[NG * OUTD];
__device__ unsigned g_pmax[NG * OUTD], g_pmin[NG * OUTD];
__device__ float    g_pcnt[NG];

// One big pool for node-feature buffers.
#define OFF_A4  0
#define OFF_B4  (OFF_A4 + NPAD * 4)
#define OFF_C4  (OFF_B4 + NPAD * 4)
#define OFF_D4  (OFF_C4 + NPAD * 4)
#define OFF_H1  (OFF_D4 + NPAD * 4)
#define OFF_H2  (OFF_H1 + NPAD * 64)
#define OFF_TB  (OFF_H2 + NPAD * 64)
#define OFF_TC  (OFF_TB + NPAD * 64)
#define OFF_TD  (OFF_TC + NPAD * 64)
#define OFF_H4  (OFF_TD + NPAD * 64)
#define POOL_FLOATS (OFF_H4 + NPAD * 32)

__device__ __align__(16) float g_pool[POOL_FLOATS];

// ---------------- helpers ----------------
__device__ __forceinline__ unsigned encf(float f) {
    unsigned u = __float_as_uint(f);
    return (u & 0x80000000u) ? ~u : (u | 0x80000000u);
}
__device__ __forceinline__ float decf(unsigned u) {
    return (u & 0x80000000u) ? __uint_as_float(u & 0x7fffffffu) : __uint_as_float(~u);
}
#define ENC_NEG_INF 0x007fffffu   /* encf(-inf) */
#define ENC_POS_INF 0xff800000u   /* encf(+inf) */

// Read index i from a buffer that is either int64 or int32 (flag g_is64).
__device__ __forceinline__ int read_idx(const void* p, long long i) {
    if (g_is64) return (int)((const long long*)p)[i];
    return ((const int*)p)[i];
}

// ---------------- dtype detection ----------------
// If edge_index is int64 (values < 2^31), every odd 32-bit word is 0.
// If int32, odd words are random node indices; 128 of them all being zero
// has probability ~1e-640. Single thread, trivial cost.
__global__ void k_detect(const unsigned* __restrict__ w) {
    if (threadIdx.x == 0 && blockIdx.x == 0) {
        int is64 = 1;
        for (int i = 1; i < 256; i += 2)
            if (w[i] != 0u) { is64 = 0; break; }
        g_is64 = is64;
    }
}

// ---------------- init ----------------
__global__ void k_init() {
    int stride = gridDim.x * blockDim.x;
    for (int i = blockIdx.x * blockDim.x + threadIdx.x; i < N_NODES; i += stride) {
        g_deg[i] = 0.0f;
        g_cnt[i] = 0;
        if (i < NG * OUTD) {
            g_psum[i] = 0.0f;
            g_pmax[i] = ENC_NEG_INF;
            g_pmin[i] = ENC_POS_INF;
        }
        if (i < NG) g_pcnt[i] = 0.0f;
    }
}

__global__ void k_zero_bn() {
    int t = threadIdx.x;
    if (t < 64) { g_bnsum[t] = 0.0; g_bnss[t] = 0.0; }
}

// ---------------- graph structure ----------------
__global__ void k_deg_cnt(const void* __restrict__ ei) {
    int e = blockIdx.x * blockDim.x + threadIdx.x;
    if (e >= N_EDGES) return;
    int s = read_idx(ei, e);
    int d = read_idx(ei, (long long)N_EDGES + e);
    atomicAdd(&g_deg[s], 1.0f);
    atomicAdd(&g_cnt[d], 1);
}

__global__ void k_dinv() {
    int i = blockIdx.x * blockDim.x + threadIdx.x;
    if (i >= N_NODES) return;
    float d = g_deg[i];
    g_dinv[i] = (d > 0.0f) ? rsqrtf(d) : 0.0f;
}

__global__ void k_scan() {  // exclusive prefix over g_cnt -> g_rowptr, 1 block of 1024
    __shared__ int sums[1024];
    const int CH = (N_NODES + 1023) / 1024;
    int t = threadIdx.x;
    int start = t * CH;
    int end = min(start + CH, N_NODES);
    int s = 0;
    for (int i = start; i < end; i++) s += g_cnt[i];
    sums[t] = s;
    __syncthreads();
    for (int off = 1; off < 1024; off <<= 1) {
        int v = (t >= off) ? sums[t - off] : 0;
        __syncthreads();
        sums[t] += v;
        __syncthreads();
    }
    int excl = t ? sums[t - 1] : 0;
    for (int i = start; i < end; i++) { g_rowptr[i] = excl; excl += g_cnt[i]; }
    if (t == 1023) g_rowptr[N_NODES] = sums[1023];
}

__global__ void k_cursor() {
    int i = blockIdx.x * blockDim.x + threadIdx.x;
    if (i < N_NODES) g_cursor[i] = g_rowptr[i];
}

__global__ void k_fill(const void* __restrict__ ei) {
    int e = blockIdx.x * blockDim.x + threadIdx.x;
    if (e >= N_EDGES) return;
    int s = read_idx(ei, e);
    int d = read_idx(ei, (long long)N_EDGES + e);
    float w = -g_dinv[s] * g_dinv[d];
    int pos = atomicAdd(&g_cursor[d], 1);
    g_csrc[pos] = s;
    g_cw[pos] = w;
}

// ---------------- layer 1 (F=4 padded) ----------------
__global__ void k_copyx(const float* __restrict__ x, float* __restrict__ a4) {
    int n = blockIdx.x * blockDim.x + threadIdx.x;
    if (n >= N_NODES) return;
    float4 v;
    v.x = x[3 * n + 0];
    v.y = x[3 * n + 1];
    v.z = x[3 * n + 2];
    v.w = 0.0f;
    *(float4*)&a4[4 * n] = v;
}

template <bool SUB>
__global__ void k_prop4(const float* __restrict__ hin, const float* __restrict__ sub,
                        float* __restrict__ hout, float scale) {
    int n = blockIdx.x * blockDim.x + threadIdx.x;
    if (n >= N_NODES) return;
    int b = g_rowptr[n], e = g_rowptr[n + 1];
    float4 acc = {0, 0, 0, 0};
    for (int i = b; i < e; i++) {
        int s = g_csrc[i];
        float w = g_cw[i];
        float4 v = *(const float4*)&hin[(size_t)s * 4];
        acc.x += w * v.x; acc.y += w * v.y; acc.z += w * v.z; acc.w += w * v.w;
    }
    float4 o;
    if (SUB) {
        float4 sv = *(const float4*)&sub[(size_t)n * 4];
        o.x = scale * acc.x - sv.x; o.y = scale * acc.y - sv.y;
        o.z = scale * acc.z - sv.z; o.w = scale * acc.w - sv.w;
    } else {
        o.x = scale * acc.x; o.y = scale * acc.y; o.z = scale * acc.z; o.w = scale * acc.w;
    }
    *(float4*)&hout[(size_t)n * 4] = o;
}

__global__ void k_combine1(const float* __restrict__ t0, const float* __restrict__ t1,
                           const float* __restrict__ t2, const float* __restrict__ t3,
                           const float* __restrict__ W, const float* __restrict__ b,
                           float* __restrict__ hout) {
    int idx = blockIdx.x * blockDim.x + threadIdx.x;
    int n = idx >> 6, o = idx & 63;
    if (n >= N_NODES) return;
    const float* tx[4] = {t0, t1, t2, t3};
    float acc = b[o];
#pragma unroll
    for (int k = 0; k < 4; k++) {
#pragma unroll
        for (int i = 0; i < 3; i++)
            acc += tx[k][(size_t)n * 4 + i] * W[(k * 3 + i) * 64 + o];
    }
    hout[(size_t)n * 64 + o] = (acc >= 0.0f) ? acc : 0.01f * acc;
}

// ---------------- F=64 propagation ----------------
template <bool SUB>
__global__ void k_prop64(const float* __restrict__ hin, const float* __restrict__ sub,
                         float* __restrict__ hout, float scale) {
    int n = (blockIdx.x * blockDim.x + threadIdx.x) >> 5;
    if (n >= N_NODES) return;
    int lane = threadIdx.x & 31;
    int b = g_rowptr[n], e = g_rowptr[n + 1];
    float ax = 0.0f, ay = 0.0f;
    for (int base = b; base < e; base += 32) {
        int i = base + lane;
        int s = 0; float w = 0.0f;
        if (i < e) { s = g_csrc[i]; w = g_cw[i]; }
        int m = min(32, e - base);
        for (int j = 0; j < m; j++) {
            int sj = __shfl_sync(0xffffffffu, s, j);
            float wj = __shfl_sync(0xffffffffu, w, j);
            float2 hv = *(const float2*)&hin[(size_t)sj * 64 + lane * 2];
            ax += wj * hv.x;
            ay += wj * hv.y;
        }
    }
    float2 o;
    if (SUB) {
        float2 sv = *(const float2*)&sub[(size_t)n * 64 + lane * 2];
        o.x = scale * ax - sv.x; o.y = scale * ay - sv.y;
    } else {
        o.x = scale * ax; o.y = scale * ay;
    }
    *(float2*)&hout[(size_t)n * 64 + lane * 2] = o;
}

// ---------------- combine: out = bias + sum_k Tx_k @ W_k ----------------
template <int FOUT, bool LRELU>
__global__ void k_combine(const float* __restrict__ t0, const float* __restrict__ t1,
                          const float* __restrict__ t2, const float* __restrict__ t3,
                          const float* __restrict__ W, const float* __restrict__ bias,
                          float* __restrict__ hout) {
    constexpr int BX = FOUT / 4;       // 16 or 8
    constexpr int BY = 256 / BX;       // 16 or 32
    constexpr int NODES = BY * 4;      // 64 or 128
    __shared__ float As[NODES * 64];
    __shared__ float Ws[64 * FOUT];
    int t = threadIdx.x;
    int tx = t % BX, ty = t / BX;
    int nodeBase = blockIdx.x * NODES;
    float acc[4][4] = {};
    const float* txs[4] = {t0, t1, t2, t3};
#pragma unroll
    for (int k = 0; k < 4; k++) {
        __syncthreads();
        const float4* src = (const float4*)(txs[k] + (size_t)nodeBase * 64);
#pragma unroll
        for (int j = 0; j < NODES * 16 / 256; j++)
            ((float4*)As)[t + j * 256] = src[t + j * 256];
        const float4* wsrc = (const float4*)(W + k * 64 * FOUT);
#pragma unroll
        for (int j = 0; j < 64 * FOUT / 4 / 256; j++)
            ((float4*)Ws)[t + j * 256] = wsrc[t + j * 256];
        __syncthreads();
        for (int i = 0; i < 64; i++) {
            float4 bv = *(const float4*)&Ws[i * FOUT + tx * 4];
            float a[4];
#pragma unroll
            for (int r = 0; r < 4; r++) a[r] = As[(ty * 4 + r) * 64 + i];
#pragma unroll
            for (int r = 0; r < 4; r++) {
                acc[r][0] += a[r] * bv.x;
                acc[r][1] += a[r] * bv.y;
                acc[r][2] += a[r] * bv.z;
                acc[r][3] += a[r] * bv.w;
            }
        }
    }
    float4 bb = *(const float4*)&bias[tx * 4];
#pragma unroll
    for (int r = 0; r < 4; r++) {
        int node = nodeBase + ty * 4 + r;
        if (node < N_NODES) {
            float4 v;
            v.x = acc[r][0] + bb.x;
            v.y = acc[r][1] + bb.y;
            v.z = acc[r][2] + bb.z;
            v.w = acc[r][3] + bb.w;
            if (LRELU) {
                v.x = (v.x >= 0.0f) ? v.x : 0.01f * v.x;
                v.y = (v.y >= 0.0f) ? v.y : 0.01f * v.y;
                v.z = (v.z >= 0.0f) ? v.z : 0.01f * v.z;
                v.w = (v.w >= 0.0f) ? v.w : 0.01f * v.w;
            }
            *(float4*)&hout[(size_t)node * FOUT + tx * 4] = v;
        }
    }
}

// ---------------- batch-norm ----------------
__global__ void k_bnstats(const float* __restrict__ h) {
    int gw = (blockIdx.x * blockDim.x + threadIdx.x) >> 5;
    int lane = threadIdx.x & 31;
    int nw = (gridDim.x * blockDim.x) >> 5;
    double s0 = 0, s1 = 0, q0 = 0, q1 = 0;
    for (int n = gw; n < N_NODES; n += nw) {
        float2 v = *(const float2*)&h[(size_t)n * 64 + lane * 2];
        s0 += v.x; s1 += v.y;
        q0 += (double)v.x * v.x; q1 += (double)v.y * v.y;
    }
    atomicAdd(&g_bnsum[lane * 2 + 0], s0);
    atomicAdd(&g_bnsum[lane * 2 + 1], s1);
    atomicAdd(&g_bnss[lane * 2 + 0], q0);
    atomicAdd(&g_bnss[lane * 2 + 1], q1);
}

__global__ void k_bnapply(float* __restrict__ h, const float* __restrict__ g,
                          const float* __restrict__ bt) {
    __shared__ float sc[64], sh[64];
    int t = threadIdx.x;
    if (t < 64) {
        double mu = g_bnsum[t] / (double)N_NODES;
        double var = g_bnss[t] / (double)N_NODES - mu * mu;
        if (var < 0.0) var = 0.0;
        double inv = rsqrt(var + 1e-5);
        sc[t] = (float)((double)g[t] * inv);
        sh[t] = (float)((double)bt[t] - mu * (double)g[t] * inv);
    }
    __syncthreads();
    int total = N_NODES * 16;  // float4 count
    int stride = gridDim.x * blockDim.x;
    for (int idx = blockIdx.x * blockDim.x + threadIdx.x; idx < total; idx += stride) {
        int c4 = (idx & 15) * 4;
        float4 v = ((float4*)h)[idx];
        v.x = v.x * sc[c4 + 0] + sh[c4 + 0];
        v.y = v.y * sc[c4 + 1] + sh[c4 + 1];
        v.z = v.z * sc[c4 + 2] + sh[c4 + 2];
        v.w = v.w * sc[c4 + 3] + sh[c4 + 3];
        ((float4*)h)[idx] = v;
    }
}

// ---------------- normalize + pooling ----------------
__global__ void k_norm_pool(const float* __restrict__ h, const void* __restrict__ batch) {
    int n = (blockIdx.x * blockDim.x + threadIdx.x) >> 5;
    if (n >= N_NODES) return;
    int lane = threadIdx.x & 31;
    float v = h[(size_t)n * 32 + lane];
    float sq = v * v;
#pragma unroll
    for (int o = 16; o; o >>= 1) sq += __shfl_xor_sync(0xffffffffu, sq, o);
    float norm = fmaxf(sqrtf(sq), 1e-12f);
    v = v / norm;
    int gidx = read_idx(batch, n);
    atomicAdd(&g_psum[gidx * 32 + lane], v);
    atomicMax(&g_pmax[gidx * 32 + lane], encf(v));
    atomicMin(&g_pmin[gidx * 32 + lane], encf(v));
    if (lane == 0) atomicAdd(&g_pcnt[gidx], 1.0f);
}

__global__ void k_finalize(float* __restrict__ out) {
    int idx = blockIdx.x * blockDim.x + threadIdx.x;
    if (idx >= NG * 32) return;
    int g = idx >> 5, c = idx & 31;
    float s = g_psum[g * 32 + c];
    float cnt = fmaxf(g_pcnt[g], 1.0f);
    out[g * 128 + c] = s / cnt;
    out[g * 128 + 32 + c] = decf(g_pmax[g * 32 + c]);
    out[g * 128 + 64 + c] = decf(g_pmin[g * 32 + c]);
    out[g * 128 + 96 + c] = s;
}

// ---------------- host ----------------
extern "C" void kernel_launch(void* const* d_in, const int* in_sizes, int n_in,
                              void* d_out, int out_size) {
    const float* x      = (const float*)d_in[0];
    const void* ei      = d_in[1];
    const void* bat     = d_in[2];
    const float* W1 = (const float*)d_in[3];  const float* bc1 = (const float*)d_in[4];
    const float* W2 = (const float*)d_in[5];  const float* bc2 = (const float*)d_in[6];
    const float* W3 = (const float*)d_in[7];  const float* bc3 = (const float*)d_in[8];
    const float* W4 = (const float*)d_in[9];  const float* bc4 = (const float*)d_in[10];
    const float* g1 = (const float*)d_in[11]; const float* bt1 = (const float*)d_in[12];
    const float* g2 = (const float*)d_in[13]; const float* bt2 = (const float*)d_in[14];
    const float* g3 = (const float*)d_in[15]; const float* bt3 = (const float*)d_in[16];
    float* out = (float*)d_out;

    void* poolv = nullptr;
    cudaGetSymbolAddress(&poolv, g_pool);
    float* pool = (float*)poolv;
    float* A4 = pool + OFF_A4;
    float* B4 = pool + OFF_B4;
    float* C4 = pool + OFF_C4;
    float* D4 = pool + OFF_D4;
    float* H1 = pool + OFF_H1;
    float* H2 = pool + OFF_H2;
    float* TB = pool + OFF_TB;
    float* TC = pool + OFF_TC;
    float* TD = pool + OFF_TD;
    float* H4 = pool + OFF_H4;

    const int NB_N  = (N_NODES + 255) / 256;       // thread-per-node grids
    const int NB_E  = (N_EDGES + 255) / 256;       // thread-per-edge grids
    const int NB_W  = (N_NODES * 32 + 255) / 256;  // warp-per-node grids

    // --- dtype probe + graph structure (rebuilt every replay) ---
    k_detect<<<1, 32>>>((const unsigned*)ei);
    k_init<<<512, 256>>>();
    k_deg_cnt<<<NB_E, 256>>>(ei);
    k_dinv<<<NB_N, 256>>>();
    k_scan<<<1, 1024>>>();
    k_cursor<<<NB_N, 256>>>();
    k_fill<<<NB_E, 256>>>(ei);

    // --- layer 1: 3 -> 64 ---
    k_copyx<<<NB_N, 256>>>(x, A4);
    k_prop4<false><<<NB_N, 256>>>(A4, nullptr, B4, 1.0f);
    k_prop4<true><<<NB_N, 256>>>(B4, A4, C4, 2.0f);
    k_prop4<true><<<NB_N, 256>>>(C4, B4, D4, 2.0f);
    k_combine1<<<(N_NODES * 64 + 255) / 256, 256>>>(A4, B4, C4, D4, W1, bc1, H1);
    k_zero_bn<<<1, 64>>>();
    k_bnstats<<<592, 256>>>(H1);
    k_bnapply<<<1024, 256>>>(H1, g1, bt1);

    // --- layer 2: 64 -> 64 ---
    k_prop64<false><<<NB_W, 256>>>(H1, nullptr, TB, 1.0f);
    k_prop64<true><<<NB_W, 256>>>(TB, H1, TC, 2.0f);
    k_prop64<true><<<NB_W, 256>>>(TC, TB, TD, 2.0f);
    k_combine<64, true><<<(N_NODES + 63) / 64, 256>>>(H1, TB, TC, TD, W2, bc2, H2);
    k_zero_bn<<<1, 64>>>();
    k_bnstats<<<592, 256>>>(H2);
    k_bnapply<<<1024, 256>>>(H2, g2, bt2);

    // --- layer 3: 64 -> 64 ---
    k_prop64<false><<<NB_W, 256>>>(H2, nullptr, TB, 1.0f);
    k_prop64<true><<<NB_W, 256>>>(TB, H2, TC, 2.0f);
    k_prop64<true><<<NB_W, 256>>>(TC, TB, TD, 2.0f);
    k_combine<64, true><<<(N_NODES + 63) / 64, 256>>>(H2, TB, TC, TD, W3, bc3, H1);
    k_zero_bn<<<1, 64>>>();
    k_bnstats<<<592, 256>>>(H1);
    k_bnapply<<<1024, 256>>>(H1, g3, bt3);

    // --- layer 4: 64 -> 32 (no lrelu/BN) ---
    k_prop64<false><<<NB_W, 256>>>(H1, nullptr, TB, 1.0f);
    k_prop64<true><<<NB_W, 256>>>(TB, H1, TC, 2.0f);
    k_prop64<true><<<NB_W, 256>>>(TC, TB, TD, 2.0f);
    k_combine<32, false><<<(N_NODES + 127) / 128, 256>>>(H1, TB, TC, TD, W4, bc4, H4);

    // --- normalize + pool ---
    k_norm_pool<<<NB_W, 256>>>(H4, bat);
    k_finalize<<<(NG * 32 + 255) / 256, 256>>>(out);
}

// round 3
// speedup vs baseline: 1.4099x; 1.4099x over previous
#include <cuda_runtime.h>

#define N_NODES 100000
#define N_EDGES 1600000
#define NG 64
#define OUTD 32
#define NPAD (N_NODES + 128)

// ---------------- static scratch ----------------
__device__ int      g_degs[N_NODES];      // out-degree (over src)
__device__ int      g_cnt[N_NODES];       // in-degree (over dst)
__device__ float    g_dinv[N_NODES];
__device__ int      g_rowptr[N_NODES + 1];
__device__ int      g_cursor[N_NODES];
__device__ int2     g_edge[N_EDGES];      // {src, __float_as_int(w)}
__device__ int      g_is64;

__device__ double   g_bnsum[3 * 64], g_bnss[3 * 64];
__device__ float    g_psum[NG * OUTD];
__device__ unsigned g_pmax[NG * OUTD], g_pmin[NG * OUTD];
__device__ float    g_pcnt[NG];

#define OFF_A4  0
#define OFF_B4  (OFF_A4 + NPAD * 4)
#define OFF_C4  (OFF_B4 + NPAD * 4)
#define OFF_D4  (OFF_C4 + NPAD * 4)
#define OFF_H1  (OFF_D4 + NPAD * 4)
#define OFF_H2  (OFF_H1 + NPAD * 64)
#define OFF_TB  (OFF_H2 + NPAD * 64)
#define OFF_TC  (OFF_TB + NPAD * 64)
#define OFF_TD  (OFF_TC + NPAD * 64)
#define OFF_H4  (OFF_TD + NPAD * 64)
#define POOL_FLOATS (OFF_H4 + NPAD * 32)

__device__ __align__(16) float g_pool[POOL_FLOATS];

// ---------------- helpers ----------------
__device__ __forceinline__ unsigned encf(float f) {
    unsigned u = __float_as_uint(f);
    return (u & 0x80000000u) ? ~u : (u | 0x80000000u);
}
__device__ __forceinline__ float decf(unsigned u) {
    return (u & 0x80000000u) ? __uint_as_float(u & 0x7fffffffu) : __uint_as_float(~u);
}
#define ENC_NEG_INF 0x007fffffu
#define ENC_POS_INF 0xff800000u

__device__ __forceinline__ int read_idx(const void* p, long long i) {
    if (g_is64) return (int)((const long long*)p)[i];
    return ((const int*)p)[i];
}

// ---------------- dtype detection ----------------
__global__ void k_detect(const unsigned* __restrict__ w) {
    if (threadIdx.x == 0 && blockIdx.x == 0) {
        int is64 = 1;
        for (int i = 1; i < 256; i += 2)
            if (w[i] != 0u) { is64 = 0; break; }
        g_is64 = is64;
    }
}

// ---------------- init ----------------
__global__ void k_init() {
    int stride = gridDim.x * blockDim.x;
    for (int i = blockIdx.x * blockDim.x + threadIdx.x; i < N_NODES; i += stride) {
        g_degs[i] = 0;
        g_cnt[i] = 0;
        if (i < 3 * 64) { g_bnsum[i] = 0.0; g_bnss[i] = 0.0; }
        if (i < NG * OUTD) {
            g_psum[i] = 0.0f;
            g_pmax[i] = ENC_NEG_INF;
            g_pmin[i] = ENC_POS_INF;
        }
        if (i < NG) g_pcnt[i] = 0.0f;
    }
}

// ---------------- graph structure ----------------
__global__ void k_deg_cnt(const void* __restrict__ ei) {
    int e = blockIdx.x * blockDim.x + threadIdx.x;
    if (e >= N_EDGES) return;
    int s = read_idx(ei, e);
    int d = read_idx(ei, (long long)N_EDGES + e);
    atomicAdd(&g_degs[s], 1);
    atomicAdd(&g_cnt[d], 1);
}

__global__ void k_dinv() {
    int i = blockIdx.x * blockDim.x + threadIdx.x;
    if (i >= N_NODES) return;
    int d = g_degs[i];
    g_dinv[i] = (d > 0) ? rsqrtf((float)d) : 0.0f;
}

__global__ void k_scan() {  // exclusive prefix over g_cnt -> g_rowptr + g_cursor
    __shared__ int sums[1024];
    const int CH = (N_NODES + 1023) / 1024;
    int t = threadIdx.x;
    int start = t * CH;
    int end = min(start + CH, N_NODES);
    int s = 0;
    for (int i = start; i < end; i++) s += g_cnt[i];
    sums[t] = s;
    __syncthreads();
    for (int off = 1; off < 1024; off <<= 1) {
        int v = (t >= off) ? sums[t - off] : 0;
        __syncthreads();
        sums[t] += v;
        __syncthreads();
    }
    int excl = t ? sums[t - 1] : 0;
    for (int i = start; i < end; i++) {
        g_rowptr[i] = excl;
        g_cursor[i] = excl;
        excl += g_cnt[i];
    }
    if (t == 1023) g_rowptr[N_NODES] = sums[1023];
}

__global__ void k_fill(const void* __restrict__ ei) {
    int e = blockIdx.x * blockDim.x + threadIdx.x;
    if (e >= N_EDGES) return;
    int s = read_idx(ei, e);
    int d = read_idx(ei, (long long)N_EDGES + e);
    float w = -g_dinv[s] * g_dinv[d];
    int pos = atomicAdd(&g_cursor[d], 1);
    g_edge[pos] = make_int2(s, __float_as_int(w));
}

// ---------------- layer 1 (F=4 padded) ----------------
__global__ void k_copyx(const float* __restrict__ x, float* __restrict__ a4) {
    int n = blockIdx.x * blockDim.x + threadIdx.x;
    if (n >= N_NODES) return;
    float4 v;
    v.x = x[3 * n + 0];
    v.y = x[3 * n + 1];
    v.z = x[3 * n + 2];
    v.w = 0.0f;
    *(float4*)&a4[4 * n] = v;
}

template <bool SUB>
__global__ void k_prop4(const float* __restrict__ hin, const float* __restrict__ sub,
                        float* __restrict__ hout, float scale) {
    int n = blockIdx.x * blockDim.x + threadIdx.x;
    if (n >= N_NODES) return;
    int b = g_rowptr[n], e = g_rowptr[n + 1];
    float4 acc = {0, 0, 0, 0};
    int i = b;
    for (; i + 4 <= e; i += 4) {
        int2 e0 = g_edge[i], e1 = g_edge[i + 1], e2 = g_edge[i + 2], e3 = g_edge[i + 3];
        float4 v0 = *(const float4*)&hin[(size_t)e0.x * 4];
        float4 v1 = *(const float4*)&hin[(size_t)e1.x * 4];
        float4 v2 = *(const float4*)&hin[(size_t)e2.x * 4];
        float4 v3 = *(const float4*)&hin[(size_t)e3.x * 4];
        float w0 = __int_as_float(e0.y), w1 = __int_as_float(e1.y);
        float w2 = __int_as_float(e2.y), w3 = __int_as_float(e3.y);
        acc.x += w0 * v0.x + w1 * v1.x + w2 * v2.x + w3 * v3.x;
        acc.y += w0 * v0.y + w1 * v1.y + w2 * v2.y + w3 * v3.y;
        acc.z += w0 * v0.z + w1 * v1.z + w2 * v2.z + w3 * v3.z;
        acc.w += w0 * v0.w + w1 * v1.w + w2 * v2.w + w3 * v3.w;
    }
    for (; i < e; i++) {
        int2 ed = g_edge[i];
        float w = __int_as_float(ed.y);
        float4 v = *(const float4*)&hin[(size_t)ed.x * 4];
        acc.x += w * v.x; acc.y += w * v.y; acc.z += w * v.z; acc.w += w * v.w;
    }
    float4 o;
    if (SUB) {
        float4 sv = *(const float4*)&sub[(size_t)n * 4];
        o.x = scale * acc.x - sv.x; o.y = scale * acc.y - sv.y;
        o.z = scale * acc.z - sv.z; o.w = scale * acc.w - sv.w;
    } else {
        o.x = scale * acc.x; o.y = scale * acc.y; o.z = scale * acc.z; o.w = scale * acc.w;
    }
    *(float4*)&hout[(size_t)n * 4] = o;
}

// combine1: 64 nodes/block, fused BN stats (layer 0)
__global__ void k_combine1(const float* __restrict__ t0, const float* __restrict__ t1,
                           const float* __restrict__ t2, const float* __restrict__ t3,
                           const float* __restrict__ W, const float* __restrict__ b,
                           float* __restrict__ hout) {
    __shared__ float S[4][256];
    __shared__ float cs[64], css[64];
    int t = threadIdx.x;
    int base = blockIdx.x * 64;
    if (t < 64) { cs[t] = 0.0f; css[t] = 0.0f; }
    {
        int k = t >> 6, idx = t & 63;
        const float* txk = (k == 0) ? t0 : (k == 1) ? t1 : (k == 2) ? t2 : t3;
        ((float4*)S[k])[idx] = ((const float4*)(txk + (size_t)base * 4))[idx];
    }
    __syncthreads();
    int o = t & 63, r4 = t >> 6;
    float wr[4][3];
#pragma unroll
    for (int k = 0; k < 4; k++)
#pragma unroll
        for (int i = 0; i < 3; i++) wr[k][i] = W[(k * 3 + i) * 64 + o];
    float bo = b[o];
    float s = 0.0f, ss = 0.0f;
#pragma unroll
    for (int q = 0; q < 16; q++) {
        int nl = q * 4 + r4;
        int n = base + nl;
        float acc = bo;
#pragma unroll
        for (int k = 0; k < 4; k++)
            acc += S[k][nl * 4 + 0] * wr[k][0] + S[k][nl * 4 + 1] * wr[k][1] +
                   S[k][nl * 4 + 2] * wr[k][2];
        acc = (acc >= 0.0f) ? acc : 0.01f * acc;
        if (n < N_NODES) {
            hout[(size_t)n * 64 + o] = acc;
            s += acc;
            ss += acc * acc;
        }
    }
    atomicAdd(&cs[o], s);
    atomicAdd(&css[o], ss);
    __syncthreads();
    if (t < 64) {
        atomicAdd(&g_bnsum[t], (double)cs[t]);
        atomicAdd(&g_bnss[t], (double)css[t]);
    }
}

// ---------------- F=64 propagation: 2 nodes per warp ----------------
template <bool SUB>
__global__ void k_prop64(const float* __restrict__ hin, const float* __restrict__ sub,
                         float* __restrict__ hout, float scale) {
    int w_id = (blockIdx.x * blockDim.x + threadIdx.x) >> 5;
    int lane = threadIdx.x & 31;
    int half = lane >> 4, hl = lane & 15;
    int n = w_id * 2 + half;
    if (n >= N_NODES) return;  // N even -> whole warp exits together
    unsigned hmask = 0xFFFFu << (half * 16);
    int sb = half * 16;
    int b = g_rowptr[n];
    int cnt = g_rowptr[n + 1] - b;
    int ocnt = __shfl_xor_sync(0xffffffffu, cnt, 16);
    int mx = max(cnt, ocnt);
    float4 acc = {0, 0, 0, 0};
    for (int base = 0; base < mx; base += 16) {
        int2 ed = make_int2(0, 0);
        if (base + hl < cnt) ed = g_edge[b + base + hl];
        int m = min(16, cnt - base);
        int j = 0;
        for (; j + 4 <= m; j += 4) {
            int s0 = __shfl_sync(hmask, ed.x, sb + j + 0);
            int s1 = __shfl_sync(hmask, ed.x, sb + j + 1);
            int s2 = __shfl_sync(hmask, ed.x, sb + j + 2);
            int s3 = __shfl_sync(hmask, ed.x, sb + j + 3);
            float w0 = __int_as_float(__shfl_sync(hmask, ed.y, sb + j + 0));
            float w1 = __int_as_float(__shfl_sync(hmask, ed.y, sb + j + 1));
            float w2 = __int_as_float(__shfl_sync(hmask, ed.y, sb + j + 2));
            float w3 = __int_as_float(__shfl_sync(hmask, ed.y, sb + j + 3));
            float4 v0 = *(const float4*)&hin[(size_t)s0 * 64 + hl * 4];
            float4 v1 = *(const float4*)&hin[(size_t)s1 * 64 + hl * 4];
            float4 v2 = *(const float4*)&hin[(size_t)s2 * 64 + hl * 4];
            float4 v3 = *(const float4*)&hin[(size_t)s3 * 64 + hl * 4];
            acc.x += w0 * v0.x + w1 * v1.x + w2 * v2.x + w3 * v3.x;
            acc.y += w0 * v0.y + w1 * v1.y + w2 * v2.y + w3 * v3.y;
            acc.z += w0 * v0.z + w1 * v1.z + w2 * v2.z + w3 * v3.z;
            acc.w += w0 * v0.w + w1 * v1.w + w2 * v2.w + w3 * v3.w;
        }
        for (; j < m; j++) {
            int s0 = __shfl_sync(hmask, ed.x, sb + j);
            float w0 = __int_as_float(__shfl_sync(hmask, ed.y, sb + j));
            float4 v0 = *(const float4*)&hin[(size_t)s0 * 64 + hl * 4];
            acc.x += w0 * v0.x; acc.y += w0 * v0.y;
            acc.z += w0 * v0.z; acc.w += w0 * v0.w;
        }
    }
    float4 o;
    if (SUB) {
        float4 sv = *(const float4*)&sub[(size_t)n * 64 + hl * 4];
        o.x = scale * acc.x - sv.x; o.y = scale * acc.y - sv.y;
        o.z = scale * acc.z - sv.z; o.w = scale * acc.w - sv.w;
    } else {
        o.x = scale * acc.x; o.y = scale * acc.y;
        o.z = scale * acc.z; o.w = scale * acc.w;
    }
    *(float4*)&hout[(size_t)n * 64 + hl * 4] = o;
}

// ---------------- combine: out = bias + sum_k Tx_k @ W_k (+lrelu, +BN stats) ----------------
template <int FOUT, bool LRELU, int LAYER>
__global__ void k_combine(const float* __restrict__ t0, const float* __restrict__ t1,
                          const float* __restrict__ t2, const float* __restrict__ t3,
                          const float* __restrict__ W, const float* __restrict__ bias,
                          float* __restrict__ hout) {
    constexpr int BX = FOUT / 4;       // 16 or 8
    constexpr int BY = 256 / BX;       // 16 or 32
    constexpr int NODES = BY * 4;      // 64 or 128
    __shared__ float As[NODES * 64];
    __shared__ float Ws[64 * FOUT];
    __shared__ float cs[64], css[64];
    int t = threadIdx.x;
    int tx = t % BX, ty = t / BX;
    int nodeBase = blockIdx.x * NODES;
    if (LRELU && t < 64) { cs[t] = 0.0f; css[t] = 0.0f; }
    float acc[4][4] = {};
#pragma unroll
    for (int k = 0; k < 4; k++) {
        __syncthreads();
        const float* txk = (k == 0) ? t0 : (k == 1) ? t1 : (k == 2) ? t2 : t3;
        const float4* src = (const float4*)(txk + (size_t)nodeBase * 64);
#pragma unroll
        for (int j = 0; j < NODES * 16 / 256; j++)
            ((float4*)As)[t + j * 256] = src[t + j * 256];
        const float4* wsrc = (const float4*)(W + k * 64 * FOUT);
#pragma unroll
        for (int j = 0; j < 64 * FOUT / 4 / 256; j++)
            ((float4*)Ws)[t + j * 256] = wsrc[t + j * 256];
        __syncthreads();
        for (int i = 0; i < 64; i++) {
            float4 bv = *(const float4*)&Ws[i * FOUT + tx * 4];
            float a[4];
#pragma unroll
            for (int r = 0; r < 4; r++) a[r] = As[(ty * 4 + r) * 64 + i];
#pragma unroll
            for (int r = 0; r < 4; r++) {
                acc[r][0] += a[r] * bv.x;
                acc[r][1] += a[r] * bv.y;
                acc[r][2] += a[r] * bv.z;
                acc[r][3] += a[r] * bv.w;
            }
        }
    }
    float4 bb = *(const float4*)&bias[tx * 4];
    float ps[4] = {0, 0, 0, 0}, pss[4] = {0, 0, 0, 0};
#pragma unroll
    for (int r = 0; r < 4; r++) {
        int node = nodeBase + ty * 4 + r;
        if (node < N_NODES) {
            float4 v;
            v.x = acc[r][0] + bb.x;
            v.y = acc[r][1] + bb.y;
            v.z = acc[r][2] + bb.z;
            v.w = acc[r][3] + bb.w;
            if (LRELU) {
                v.x = (v.x >= 0.0f) ? v.x : 0.01f * v.x;
                v.y = (v.y >= 0.0f) ? v.y : 0.01f * v.y;
                v.z = (v.z >= 0.0f) ? v.z : 0.01f * v.z;
                v.w = (v.w >= 0.0f) ? v.w : 0.01f * v.w;
                ps[0] += v.x; pss[0] += v.x * v.x;
                ps[1] += v.y; pss[1] += v.y * v.y;
                ps[2] += v.z; pss[2] += v.z * v.z;
                ps[3] += v.w; pss[3] += v.w * v.w;
            }
            *(float4*)&hout[(size_t)node * FOUT + tx * 4] = v;
        }
    }
    if (LRELU) {
#pragma unroll
        for (int c = 0; c < 4; c++) {
            atomicAdd(&cs[tx * 4 + c], ps[c]);
            atomicAdd(&css[tx * 4 + c], pss[c]);
        }
        __syncthreads();
        if (t < 64) {
            atomicAdd(&g_bnsum[LAYER * 64 + t], (double)cs[t]);
            atomicAdd(&g_bnss[LAYER * 64 + t], (double)css[t]);
        }
    }
}

// ---------------- batch-norm apply ----------------
__global__ void k_bnapply(float* __restrict__ h, const float* __restrict__ g,
                          const float* __restrict__ bt, int layer) {
    __shared__ float sc[64], sh[64];
    int t = threadIdx.x;
    if (t < 64) {
        double mu = g_bnsum[layer * 64 + t] / (double)N_NODES;
        double var = g_bnss[layer * 64 + t] / (double)N_NODES - mu * mu;
        if (var < 0.0) var = 0.0;
        double inv = rsqrt(var + 1e-5);
        sc[t] = (float)((double)g[t] * inv);
        sh[t] = (float)((double)bt[t] - mu * (double)g[t] * inv);
    }
    __syncthreads();
    int total = N_NODES * 16;  // float4 count
    int stride = gridDim.x * blockDim.x;
    for (int idx = blockIdx.x * blockDim.x + threadIdx.x; idx < total; idx += stride) {
        int c4 = (idx & 15) * 4;
        float4 v = ((float4*)h)[idx];
        v.x = v.x * sc[c4 + 0] + sh[c4 + 0];
        v.y = v.y * sc[c4 + 1] + sh[c4 + 1];
        v.z = v.z * sc[c4 + 2] + sh[c4 + 2];
        v.w = v.w * sc[c4 + 3] + sh[c4 + 3];
        ((float4*)h)[idx] = v;
    }
}

// ---------------- normalize + pooling ----------------
__global__ void k_norm_pool(const float* __restrict__ h, const void* __restrict__ batch) {
    int n = (blockIdx.x * blockDim.x + threadIdx.x) >> 5;
    if (n >= N_NODES) return;
    int lane = threadIdx.x & 31;
    float v = h[(size_t)n * 32 + lane];
    float sq = v * v;
#pragma unroll
    for (int o = 16; o; o >>= 1) sq += __shfl_xor_sync(0xffffffffu, sq, o);
    float norm = fmaxf(sqrtf(sq), 1e-12f);
    v = v / norm;
    int gidx = read_idx(batch, n);
    atomicAdd(&g_psum[gidx * 32 + lane], v);
    atomicMax(&g_pmax[gidx * 32 + lane], encf(v));
    atomicMin(&g_pmin[gidx * 32 + lane], encf(v));
    if (lane == 0) atomicAdd(&g_pcnt[gidx], 1.0f);
}

__global__ void k_finalize(float* __restrict__ out) {
    int idx = blockIdx.x * blockDim.x + threadIdx.x;
    if (idx >= NG * 32) return;
    int g = idx >> 5, c = idx & 31;
    float s = g_psum[g * 32 + c];
    float cnt = fmaxf(g_pcnt[g], 1.0f);
    out[g * 128 + c] = s / cnt;
    out[g * 128 + 32 + c] = decf(g_pmax[g * 32 + c]);
    out[g * 128 + 64 + c] = decf(g_pmin[g * 32 + c]);
    out[g * 128 + 96 + c] = s;
}

// ---------------- host ----------------
extern "C" void kernel_launch(void* const* d_in, const int* in_sizes, int n_in,
                              void* d_out, int out_size) {
    const float* x  = (const float*)d_in[0];
    const void* ei  = d_in[1];
    const void* bat = d_in[2];
    const float* W1 = (const float*)d_in[3];  const float* bc1 = (const float*)d_in[4];
    const float* W2 = (const float*)d_in[5];  const float* bc2 = (const float*)d_in[6];
    const float* W3 = (const float*)d_in[7];  const float* bc3 = (const float*)d_in[8];
    const float* W4 = (const float*)d_in[9];  const float* bc4 = (const float*)d_in[10];
    const float* g1 = (const float*)d_in[11]; const float* bt1 = (const float*)d_in[12];
    const float* g2 = (const float*)d_in[13]; const float* bt2 = (const float*)d_in[14];
    const float* g3 = (const float*)d_in[15]; const float* bt3 = (const float*)d_in[16];
    float* out = (float*)d_out;

    void* poolv = nullptr;
    cudaGetSymbolAddress(&poolv, g_pool);
    float* pool = (float*)poolv;
    float* A4 = pool + OFF_A4;
    float* B4 = pool + OFF_B4;
    float* C4 = pool + OFF_C4;
    float* D4 = pool + OFF_D4;
    float* H1 = pool + OFF_H1;
    float* H2 = pool + OFF_H2;
    float* TB = pool + OFF_TB;
    float* TC = pool + OFF_TC;
    float* TD = pool + OFF_TD;
    float* H4 = pool + OFF_H4;

    const int NB_N  = (N_NODES + 255) / 256;
    const int NB_E  = (N_EDGES + 255) / 256;
    const int NB_W2 = (N_NODES / 2 * 32 + 255) / 256;   // 2 nodes/warp
    const int NB_W  = (N_NODES * 32 + 255) / 256;       // warp/node (pool)

    // --- dtype probe + graph structure ---
    k_detect<<<1, 32>>>((const unsigned*)ei);
    k_init<<<512, 256>>>();
    k_deg_cnt<<<NB_E, 256>>>(ei);
    k_dinv<<<NB_N, 256>>>();
    k_scan<<<1, 1024>>>();
    k_fill<<<NB_E, 256>>>(ei);

    // --- layer 1: 3 -> 64 ---
    k_copyx<<<NB_N, 256>>>(x, A4);
    k_prop4<false><<<NB_N, 256>>>(A4, nullptr, B4, 1.0f);
    k_prop4<true><<<NB_N, 256>>>(B4, A4, C4, 2.0f);
    k_prop4<true><<<NB_N, 256>>>(C4, B4, D4, 2.0f);
    k_combine1<<<(N_NODES + 63) / 64, 256>>>(A4, B4, C4, D4, W1, bc1, H1);
    k_bnapply<<<1024, 256>>>(H1, g1, bt1, 0);

    // --- layer 2: 64 -> 64 ---
    k_prop64<false><<<NB_W2, 256>>>(H1, nullptr, TB, 1.0f);
    k_prop64<true><<<NB_W2, 256>>>(TB, H1, TC, 2.0f);
    k_prop64<true><<<NB_W2, 256>>>(TC, TB, TD, 2.0f);
    k_combine<64, true, 1><<<(N_NODES + 63) / 64, 256>>>(H1, TB, TC, TD, W2, bc2, H2);
    k_bnapply<<<1024, 256>>>(H2, g2, bt2, 1);

    // --- layer 3: 64 -> 64 ---
    k_prop64<false><<<NB_W2, 256>>>(H2, nullptr, TB, 1.0f);
    k_prop64<true><<<NB_W2, 256>>>(TB, H2, TC, 2.0f);
    k_prop64<true><<<NB_W2, 256>>>(TC, TB, TD, 2.0f);
    k_combine<64, true, 2><<<(N_NODES + 63) / 64, 256>>>(H2, TB, TC, TD, W3, bc3, H1);
    k_bnapply<<<1024, 256>>>(H1, g3, bt3, 2);

    // --- layer 4: 64 -> 32 ---
    k_prop64<false><<<NB_W2, 256>>>(H1, nullptr, TB, 1.0f);
    k_prop64<true><<<NB_W2, 256>>>(TB, H1, TC, 2.0f);
    k_prop64<true><<<NB_W2, 256>>>(TC, TB, TD, 2.0f);
    k_combine<32, false, 3><<<(N_NODES + 127) / 128, 256>>>(H1, TB, TC, TD, W4, bc4, H4);

    // --- normalize + pool ---
    k_norm_pool<<<NB_W, 256>>>(H4, bat);
    k_finalize<<<(NG * 32 + 255) / 256, 256>>>(out);
}